// round 17
// baseline (speedup 1.0000x reference)
#include <cuda_runtime.h>
#include <cuda_fp16.h>
#include <cstdint>
#include <math_constants.h>

// NearestEmbed via mma.sync m16n8k16 fp16 (3-pass hi/lo split) + fused argmin.
// R15 = R14 with warp tile 16x32 (acc 16 regs), 512 thr/CTA, 2 CTAs/SM
// -> 32 warps/SM (occ 50%) for latency hiding.
// score[n,k] = ||e_k||^2 - 2 * x_n . e_k
// dot = xh.eh + xh.el + xl.eh  (fp16 split, fp32 accumulate; xl.el ~ 2^-22)

#define D_DIM 256
#define K_DIM 1024
#define BMC 64                          // latents per CTA
#define THREADS 512
#define NCHUNK 64                       // 8 k-tiles x 8 d-chunks

#define A_BYTES 4096                    // A-half hi (64 lat x 32 d fp16)
#define B_BYTES 8192                    // B hi (128 codes x 32 d fp16)
#define BUF_BYTES (2 * A_BYTES + 2 * B_BYTES)   // 24576
#define SMEM_DYN (3 * BUF_BYTES)        // 73728

__device__ float g_e2[K_DIM];
__device__ uint32_t g_pAh[512 * 8 * 2048];   // [tile128][ch][g][mp][tig] fp16x2
__device__ uint32_t g_pAl[512 * 8 * 2048];
__device__ uint32_t g_pBh[64 * 2048];        // [c][g][n][tig] fp16x2
__device__ uint32_t g_pBl[64 * 2048];

__device__ __forceinline__ uint32_t smem_u32(const void* p) {
    uint32_t a;
    asm("{ .reg .u64 t; cvta.to.shared.u64 t, %1; cvt.u32.u64 %0, t; }" : "=r"(a) : "l"(p));
    return a;
}
__device__ __forceinline__ void cp16(uint32_t dst, const void* src) {
    asm volatile("cp.async.cg.shared.global [%0], [%1], 16;" :: "r"(dst), "l"(src) : "memory");
}
#define CP_COMMIT() asm volatile("cp.async.commit_group;" ::: "memory")
#define CP_WAIT(N)  asm volatile("cp.async.wait_group %0;" :: "n"(N) : "memory")

__device__ __forceinline__ void mma16(float* c, uint4 a, uint2 b) {
    asm volatile(
        "mma.sync.aligned.m16n8k16.row.col.f32.f16.f16.f32 "
        "{%0,%1,%2,%3}, {%4,%5,%6,%7}, {%8,%9}, {%0,%1,%2,%3};"
        : "+f"(c[0]), "+f"(c[1]), "+f"(c[2]), "+f"(c[3])
        : "r"(a.x), "r"(a.y), "r"(a.z), "r"(a.w), "r"(b.x), "r"(b.y));
}

__device__ __forceinline__ void split2(float v0, float v1, uint32_t& hi, uint32_t& lo) {
    __half h0 = __float2half_rn(v0);
    __half h1 = __float2half_rn(v1);
    __half l0 = __float2half_rn(v0 - __half2float(h0));
    __half l1 = __float2half_rn(v1 - __half2float(h1));
    hi = (uint32_t)__half_as_ushort(h0) | ((uint32_t)__half_as_ushort(h1) << 16);
    lo = (uint32_t)__half_as_ushort(l0) | ((uint32_t)__half_as_ushort(l1) << 16);
}

// ---------------- prep kernels ----------------
__global__ void e2_kernel(const float* __restrict__ emb) {
    int k = blockIdx.x * blockDim.x + threadIdx.x;
    float s = 0.f;
#pragma unroll 8
    for (int d = 0; d < D_DIM; ++d) {
        float v = emb[(size_t)d * K_DIM + k];
        s = fmaf(v, v, s);
    }
    g_e2[k] = s;
}

// pack x into fp16 hi/lo fragment-order A chunks (per 128-latent tile)
__global__ void packA_kernel(const float* __restrict__ x) {
    __shared__ float xs[32 * 128];
    const int ch = blockIdx.x;
    const int tile = blockIdx.y;
    const int b = tile >> 3;
    const int hw0 = (tile & 7) << 7;
    const int tid = threadIdx.x;
    const float* xb = x + ((size_t)b * D_DIM + ch * 32) * 1024 + hw0;
#pragma unroll
    for (int i = 0; i < 4; ++i) {
        int f = tid + i * 256;
        int r = f >> 5, q = (f & 31) << 2;
        *(float4*)&xs[r * 128 + q] = *(const float4*)(xb + (size_t)r * 1024 + q);
    }
    __syncthreads();
    uint4* dh = (uint4*)g_pAh + (size_t)(tile * 8 + ch) * 512;
    uint4* dl = (uint4*)g_pAl + (size_t)(tile * 8 + ch) * 512;
#pragma unroll
    for (int i = 0; i < 2; ++i) {
        int o = tid + i * 256;                  // [g][mp][tig], 512 total
        int tig = o & 3, mp = (o >> 2) & 63, g = o >> 8;
        int k2 = g * 16 + 2 * tig;
        int M0 = ((mp & 0x38) << 1) | (mp & 7);
        uint4 h, l;
        split2(xs[k2 * 128 + M0],       xs[(k2 + 1) * 128 + M0],       h.x, l.x);
        split2(xs[k2 * 128 + M0 + 8],   xs[(k2 + 1) * 128 + M0 + 8],   h.y, l.y);
        split2(xs[(k2 + 8) * 128 + M0],     xs[(k2 + 9) * 128 + M0],     h.z, l.z);
        split2(xs[(k2 + 8) * 128 + M0 + 8], xs[(k2 + 9) * 128 + M0 + 8], h.w, l.w);
        dh[o] = h;
        dl[o] = l;
    }
}

// pack emb into fp16 hi/lo fragment-order B chunks: c = kt*8+ch
__global__ void packB_kernel(const float* __restrict__ emb) {
    const int c = blockIdx.x;
    const int kt = c >> 3, ch = c & 7;
    const int k0 = kt * 128, d0 = ch * 32;
    const int tid = threadIdx.x;
    uint2* dh = (uint2*)g_pBh + (size_t)c * 1024;
    uint2* dl = (uint2*)g_pBl + (size_t)c * 1024;
#pragma unroll
    for (int i = 0; i < 4; ++i) {
        int o = tid + i * 256;                  // [g][n][tig], 1024 total
        int tig = o & 3, n = (o >> 2) & 127, g = o >> 9;
        int k2 = d0 + g * 16 + 2 * tig;
        uint2 h, l;
        split2(emb[(size_t)k2 * K_DIM + k0 + n],       emb[(size_t)(k2 + 1) * K_DIM + k0 + n], h.x, l.x);
        split2(emb[(size_t)(k2 + 8) * K_DIM + k0 + n], emb[(size_t)(k2 + 9) * K_DIM + k0 + n], h.y, l.y);
        dh[o] = h;
        dl[o] = l;
    }
}

// ---------------- main kernel ----------------
__global__ __launch_bounds__(THREADS, 2)
void vq_mma_kernel(const float* __restrict__ emb, float* __restrict__ out,
                   float* __restrict__ idx_out, int has_idx) {
    extern __shared__ char smc[];
    __shared__ float e2s[K_DIM];
    __shared__ float redv[BMC][4];
    __shared__ int redi[BMC][4];
    __shared__ int idx_s[BMC];

    const int tid = threadIdx.x;
    const int wid = tid >> 5;         // 0..15
    const int lane = tid & 31;
    const int gid = lane >> 2;
    const int tig = lane & 3;
    const int wm = wid >> 2;          // 0..3 (M, 16 rows each)
    const int wn = wid & 3;           // 0..3 (N, 32 cols each)
    const int mbw = wm * 16;
    const int nbw = wn * 32;
    const uint32_t smb = smem_u32(smc);

    const int n0 = blockIdx.x * BMC;
    const int tile128 = blockIdx.x >> 1;      // packed A tile
    const int half = blockIdx.x & 1;          // which 64-row half
    const int b = n0 >> 10;
    const int hw0 = n0 & 1023;

    // staging: chunk c -> buffer c%3; A-half slice + full B
    auto stage = [&](int c) {
        const uint32_t base = smb + (uint32_t)(c % 3) * BUF_BYTES;
        const uint4* sAh = (const uint4*)g_pAh + (size_t)(tile128 * 8 + (c & 7)) * 512;
        const uint4* sAl = (const uint4*)g_pAl + (size_t)(tile128 * 8 + (c & 7)) * 512;
        const uint4* sBh = (const uint4*)g_pBh + (size_t)c * 512;
        const uint4* sBl = (const uint4*)g_pBl + (size_t)c * 512;
        if (tid < 256) {
            // A hi: 256 uint4 (g 0..1, 128 each from the half slice)
            int g = tid >> 7;
            int off = g * 256 + half * 128 + (tid & 127);
            cp16(base + tid * 16, sAh + off);
        } else {
            int t = tid - 256;
            int g = t >> 7;
            int off = g * 256 + half * 128 + (t & 127);
            cp16(base + A_BYTES + t * 16, sAl + off);
        }
        cp16(base + 2 * A_BYTES + tid * 16, sBh + tid);
        cp16(base + 2 * A_BYTES + B_BYTES + tid * 16, sBl + tid);
    };

    for (int i = tid; i < K_DIM; i += THREADS) e2s[i] = g_e2[i];

    float best[2];
    int bidx[2];
#pragma unroll
    for (int s = 0; s < 2; ++s) { best[s] = CUDART_INF_F; bidx[s] = 0; }

    stage(0); CP_COMMIT();
    stage(1); CP_COMMIT();

    float acc[4][4];
    // A fragment index within the 64-row half: rows (mbw+gid, mbw+gid+8) in one uint4
    const int Ml0 = mbw + gid;
    const int a0i = (8 * wm + gid) * 4 + tig;        // mp_local*4 + tig, 0..127
    const int bbase = (nbw + gid) * 4 + tig;

    for (int c = 0; c < NCHUNK; ++c) {
        if ((c & 7) == 0) {
#pragma unroll
            for (int nt = 0; nt < 4; ++nt)
#pragma unroll
                for (int j = 0; j < 4; ++j) acc[nt][j] = 0.f;
        }

        if (c < NCHUNK - 1) { CP_WAIT(1); } else { CP_WAIT(0); }
        __syncthreads();
        if (c + 2 < NCHUNK) { stage(c + 2); CP_COMMIT(); }

        const char* buf = smc + (c % 3) * BUF_BYTES;
        const uint4* Ah = (const uint4*)buf;
        const uint4* Al = (const uint4*)(buf + A_BYTES);
        const uint2* Bh = (const uint2*)(buf + 2 * A_BYTES);
        const uint2* Bl = (const uint2*)(buf + 2 * A_BYTES + B_BYTES);

#pragma unroll
        for (int g = 0; g < 2; ++g) {
            uint4 ah = Ah[g * 128 + a0i];
            uint4 al = Al[g * 128 + a0i];
#pragma unroll
            for (int nt = 0; nt < 4; ++nt) {
                uint2 bh = Bh[g * 512 + bbase + nt * 32];
                uint2 bl = Bl[g * 512 + bbase + nt * 32];
                mma16(acc[nt], ah, bh);
                mma16(acc[nt], ah, bl);
                mma16(acc[nt], al, bh);
            }
        }

        if ((c & 7) == 7) {
            // fused argmin epilogue for k-tile kt = c>>3 (registers only)
            const int k0 = (c >> 3) * 128;
#pragma unroll
            for (int nt = 0; nt < 4; ++nt) {
                const int kc = k0 + nbw + nt * 8 + 2 * tig;
                const float e20 = e2s[kc], e21 = e2s[kc + 1];
                float s0 = fmaf(-2.f, acc[nt][0], e20);   // row Ml0
                float s1 = fmaf(-2.f, acc[nt][1], e21);   // row Ml0
                float s2 = fmaf(-2.f, acc[nt][2], e20);   // row Ml0+8
                float s3 = fmaf(-2.f, acc[nt][3], e21);   // row Ml0+8
                if (s0 < best[0]) { best[0] = s0; bidx[0] = kc; }
                if (s1 < best[0]) { best[0] = s1; bidx[0] = kc + 1; }
                if (s2 < best[1]) { best[1] = s2; bidx[1] = kc; }
                if (s3 < best[1]) { best[1] = s3; bidx[1] = kc + 1; }
            }
        }
    }

    // reduce across the 4 lanes of each quad (same rows, different cols)
#pragma unroll
    for (int s = 0; s < 2; ++s) {
        float v = best[s];
        int ix = bidx[s];
#pragma unroll
        for (int off = 1; off <= 2; off <<= 1) {
            float v2 = __shfl_xor_sync(0xFFFFFFFFu, v, off);
            int i2 = __shfl_xor_sync(0xFFFFFFFFu, ix, off);
            if (v2 < v || (v2 == v && i2 < ix)) { v = v2; ix = i2; }
        }
        if (tig == 0) {
            int row = Ml0 + s * 8;
            redv[row][wn] = v;
            redi[row][wn] = ix;
        }
    }
    __syncthreads();
    if (tid < BMC) {
        float bv = redv[tid][0];
        int bi = redi[tid][0];
#pragma unroll
        for (int t = 1; t < 4; ++t) {
            float v = redv[tid][t];
            int id = redi[tid][t];
            if (v < bv || (v == bv && id < bi)) { bv = v; bi = id; }
        }
        idx_s[tid] = bi;
        if (has_idx) idx_out[n0 + tid] = (float)bi;
    }
    __syncthreads();

    // gather nearest code (exact fp32), scatter to (B,D,H,W)
    for (int r = tid; r < D_DIM * BMC; r += THREADS) {
        int d = r >> 6;
        int m = r & (BMC - 1);
        out[((size_t)b * D_DIM + d) * 1024 + hw0 + m] = emb[(size_t)d * K_DIM + idx_s[m]];
    }
}

extern "C" void kernel_launch(void* const* d_in, const int* in_sizes, int n_in,
                              void* d_out, int out_size) {
    const float* x = (const float*)d_in[0];    // (64,256,32,32)
    const float* emb = (const float*)d_in[1];  // (256,1024)
    float* out = (float*)d_out;

    const int n_img = 64 * 256 * 32 * 32;
    const int n_lat = 64 * 32 * 32;
    float* idx_out = nullptr;
    int has_idx = 0;
    if (out_size >= n_img + n_lat) {
        idx_out = out + n_img;
        has_idx = 1;
    }

    cudaFuncSetAttribute(vq_mma_kernel, cudaFuncAttributeMaxDynamicSharedMemorySize, SMEM_DYN);

    e2_kernel<<<4, 256>>>(emb);
    packA_kernel<<<dim3(8, 512), 256>>>(x);
    packB_kernel<<<64, 256>>>(emb);
    vq_mma_kernel<<<1024, THREADS, SMEM_DYN>>>(emb, out, idx_out, has_idx);
}